// round 6
// baseline (speedup 1.0000x reference)
#include <cuda_runtime.h>
#include <cuda_bf16.h>
#include <math.h>
#include <stdint.h>

// Problem constants (fixed-shape problem)
#define B_  64
#define S_  512
#define H_  768
#define U_  16
#define C_  5
#define NSEG (B_ * U_)       // 1024
#define NTILE_N 12           // 768 / 64
#define NTILE_M 16           // 1024 / 64
#define NTILE_P (NTILE_N * 2)  // 24 partial slots (32-col warp slices)
#define NWPREP  576          // 24 x 24 transpose blocks

// ---------------------------------------------------------------------------
// Scratch (no allocation allowed)
// ---------------------------------------------------------------------------
__device__ __align__(16) __nv_bfloat16 g_mean_hi[NSEG * H_];
__device__ __align__(16) __nv_bfloat16 g_mean_lo[NSEG * H_];
__device__ __align__(16) __nv_bfloat16 g_wt_hi[H_ * H_];   // W_h^T: [n][k]
__device__ __align__(16) __nv_bfloat16 g_wt_lo[H_ * H_];
__device__ float g_partial[NTILE_P * NSEG * C_];

// ---------------------------------------------------------------------------
// PTX helpers (baseline PTX only — compiles for compute_103)
// ---------------------------------------------------------------------------
__device__ __forceinline__ void mma_bf16(float* c, const uint32_t* a,
                                         const uint32_t* b) {
    asm volatile(
        "mma.sync.aligned.m16n8k16.row.col.f32.bf16.bf16.f32 "
        "{%0,%1,%2,%3}, {%4,%5,%6,%7}, {%8,%9}, {%0,%1,%2,%3};\n"
        : "+f"(c[0]), "+f"(c[1]), "+f"(c[2]), "+f"(c[3])
        : "r"(a[0]), "r"(a[1]), "r"(a[2]), "r"(a[3]), "r"(b[0]), "r"(b[1]));
}
__device__ __forceinline__ void ldsm_x4(uint32_t* r, uint32_t addr) {
    asm volatile(
        "ldmatrix.sync.aligned.m8n8.x4.shared.b16 {%0,%1,%2,%3}, [%4];"
        : "=r"(r[0]), "=r"(r[1]), "=r"(r[2]), "=r"(r[3]) : "r"(addr));
}
#define CP16(dst, src) \
    asm volatile("cp.async.cg.shared.global [%0], [%1], 16;" \
                 :: "r"(dst), "l"(src))
__device__ __forceinline__ uint32_t s2u(const void* p) {
    return (uint32_t)__cvta_generic_to_shared(p);
}

// ---------------------------------------------------------------------------
// Kernel 1 (merged prep), block = 384:
//   blocks [0, NSEG): per-segment count + mean (2 row groups) + bf16 split
//   blocks [NSEG, NSEG+NWPREP): W_h transpose + bf16 split (tid<256 active)
// ---------------------------------------------------------------------------
__global__ __launch_bounds__(384) void prep_kernel(
    const float* __restrict__ hidden, const int* __restrict__ seg,
    const float* __restrict__ W) {
    const int bid = blockIdx.x;
    const int tid = threadIdx.x;

    if (bid < NSEG) {
        // ---- per-segment count (first 256 threads) ----
        __shared__ int s_lt, s_eq;
        __shared__ float4 red[192];
        const int b = bid >> 4, u = bid & 15;
        if (tid == 0) { s_lt = 0; s_eq = 0; }
        __syncthreads();
        if (tid < 256) {
            int2 v = ((const int2*)(seg + (size_t)b * S_))[tid];
            int lt = (v.x < u) + (v.y < u);
            int eq = (v.x == u) + (v.y == u);
            #pragma unroll
            for (int off = 16; off > 0; off >>= 1) {
                lt += __shfl_xor_sync(0xFFFFFFFFu, lt, off);
                eq += __shfl_xor_sync(0xFFFFFFFFu, eq, off);
            }
            if ((tid & 31) == 0) { atomicAdd(&s_lt, lt); atomicAdd(&s_eq, eq); }
        }
        __syncthreads();
        const int start = b * S_ + s_lt;
        const int cnt   = s_eq;
        const float inv = 1.0f / fmaxf((float)cnt, 1.0f);

        // ---- mean: 2 row groups of 192 column-threads ----
        const int gcol = tid % 192;
        const int grp  = tid / 192;   // 0 or 1
        const float4* __restrict__ hp =
            (const float4*)hidden + (size_t)start * (H_ / 4) + gcol;

        float4 a0 = {0,0,0,0}, a1 = {0,0,0,0};
        int r = grp;
        for (; r + 2 < cnt; r += 4) {
            float4 v0 = hp[(size_t)r * (H_ / 4)];
            float4 v1 = hp[(size_t)(r + 2) * (H_ / 4)];
            a0.x += v0.x; a0.y += v0.y; a0.z += v0.z; a0.w += v0.w;
            a1.x += v1.x; a1.y += v1.y; a1.z += v1.z; a1.w += v1.w;
        }
        if (r < cnt) {
            float4 v0 = hp[(size_t)r * (H_ / 4)];
            a0.x += v0.x; a0.y += v0.y; a0.z += v0.z; a0.w += v0.w;
        }
        a0.x += a1.x; a0.y += a1.y; a0.z += a1.z; a0.w += a1.w;

        if (grp == 1) red[gcol] = a0;
        __syncthreads();
        if (grp == 0) {
            float4 p = red[gcol];
            float m[4];
            m[0] = (a0.x + p.x) * inv;
            m[1] = (a0.y + p.y) * inv;
            m[2] = (a0.z + p.z) * inv;
            m[3] = (a0.w + p.w) * inv;

            __nv_bfloat16 hi[4], lo[4];
            #pragma unroll
            for (int i = 0; i < 4; ++i) {
                hi[i] = __float2bfloat16(m[i]);
                lo[i] = __float2bfloat16(m[i] - __bfloat162float(hi[i]));
            }
            __nv_bfloat162 ph0 = {hi[0], hi[1]}, ph1 = {hi[2], hi[3]};
            __nv_bfloat162 pl0 = {lo[0], lo[1]}, pl1 = {lo[2], lo[3]};
            uint2 uh, ul;
            uh.x = *(uint32_t*)&ph0; uh.y = *(uint32_t*)&ph1;
            ul.x = *(uint32_t*)&pl0; ul.y = *(uint32_t*)&pl1;
            ((uint2*)g_mean_hi)[(size_t)bid * (H_ / 4) + gcol] = uh;
            ((uint2*)g_mean_lo)[(size_t)bid * (H_ / 4) + gcol] = ul;
        }
    } else {
        // ---- W_h transpose + split (256 active threads) ----
        __shared__ float t[32][33];
        const int w  = bid - NSEG;
        const int n0 = (w % 24) * 32, k0 = (w / 24) * 32;
        if (tid < 256) {
            const int tx = tid & 31, ty = tid >> 5;   // 32 x 8
            #pragma unroll
            for (int r = 0; r < 32; r += 8)
                t[ty + r][tx] = W[(size_t)(k0 + ty + r) * H_ + n0 + tx];
        }
        __syncthreads();
        if (tid < 256) {
            const int tx = tid & 31, ty = tid >> 5;
            const int k = k0 + tx;
            #pragma unroll
            for (int r = 0; r < 32; r += 8) {
                const int n = n0 + ty + r;
                float v = t[tx][ty + r];
                __nv_bfloat16 hi = __float2bfloat16(v);
                __nv_bfloat16 lo = __float2bfloat16(v - __bfloat162float(hi));
                g_wt_hi[(size_t)n * H_ + k] = hi;
                g_wt_lo[(size_t)n * H_ + k] = lo;
            }
        }
    }
}

// ---------------------------------------------------------------------------
// Kernel 2: bf16x3 warp-MMA GEMM + bias + SELU + fused partial logits.
// CTA tile 64x64, block = 256 (8 warps: 4M x 2N, warp tile 16x32).
// K chunks of 32, 2-stage cp.async pipeline, ldmatrix fragment loads.
// grid = (12, 16) = 192 CTAs, 2 CTAs/SM -> 16 warps/SM.
// ---------------------------------------------------------------------------
#define TM 64
#define TN 64
#define KC 32
#define KPAD 40
#define NCHUNK (H_ / KC)   // 24

__global__ __launch_bounds__(256) void gemm_fused_kernel(
    const float* __restrict__ bias, const float* __restrict__ Wo) {
    __shared__ __align__(16) __nv_bfloat16 sA_hi[2][TM][KPAD];
    __shared__ __align__(16) __nv_bfloat16 sA_lo[2][TM][KPAD];
    __shared__ __align__(16) __nv_bfloat16 sB_hi[2][TN][KPAD];
    __shared__ __align__(16) __nv_bfloat16 sB_lo[2][TN][KPAD];
    __shared__ float sWo[TN * C_];
    __shared__ float sBias[TN];

    const int tid  = threadIdx.x;
    const int wid  = tid >> 5;
    const int lane = tid & 31;
    const int warp_m = wid & 3;     // 0..3 (16 rows each)
    const int warp_n = wid >> 2;    // 0..1 (32 cols each)
    const int n0 = blockIdx.x * TN;
    const int m0 = blockIdx.y * TM;

    for (int i = tid; i < TN * C_; i += 256) sWo[i] = Wo[(size_t)n0 * C_ + i];
    if (tid < TN) sBias[tid] = bias[n0 + tid];

    const __nv_bfloat16* __restrict__ Ahi = g_mean_hi + (size_t)m0 * H_;
    const __nv_bfloat16* __restrict__ Alo = g_mean_lo + (size_t)m0 * H_;
    const __nv_bfloat16* __restrict__ Bhi = g_wt_hi + (size_t)n0 * H_;
    const __nv_bfloat16* __restrict__ Blo = g_wt_lo + (size_t)n0 * H_;

    // per-thread copy coords: 256 16B-units per array, 1 per thread
    const int row_c = tid >> 2, u_c = (tid & 3);

    auto issue = [&](int st, int k0) {
        CP16(s2u(&sA_hi[st][row_c][u_c * 8]),
             Ahi + (size_t)row_c * H_ + k0 + u_c * 8);
        CP16(s2u(&sA_lo[st][row_c][u_c * 8]),
             Alo + (size_t)row_c * H_ + k0 + u_c * 8);
        CP16(s2u(&sB_hi[st][row_c][u_c * 8]),
             Bhi + (size_t)row_c * H_ + k0 + u_c * 8);
        CP16(s2u(&sB_lo[st][row_c][u_c * 8]),
             Blo + (size_t)row_c * H_ + k0 + u_c * 8);
    };

    issue(0, 0);
    asm volatile("cp.async.commit_group;" ::: "memory");

    float acc[4][4] = {};   // [nt][elem], warp tile 16x32

    for (int ck = 0; ck < NCHUNK; ++ck) {
        asm volatile("cp.async.wait_group 0;" ::: "memory");
        __syncthreads();
        if (ck + 1 < NCHUNK) issue((ck + 1) & 1, (ck + 1) * KC);
        asm volatile("cp.async.commit_group;" ::: "memory");

        const int st = ck & 1;
        #pragma unroll
        for (int ks = 0; ks < 2; ++ks) {
            const int kw = ks * 16;
            uint32_t ah[4], al[4], bh[2][4], bl[2][4];
            {
                int row = warp_m * 16 + (lane & 15);
                int col = kw + ((lane >> 4) << 3);
                ldsm_x4(ah, s2u(&sA_hi[st][row][col]));
                ldsm_x4(al, s2u(&sA_lo[st][row][col]));
            }
            #pragma unroll
            for (int np = 0; np < 2; ++np) {
                int row = warp_n * 32 + np * 16 + (lane & 7) +
                          ((lane >> 4) << 3);
                int col = kw + (((lane >> 3) & 1) << 3);
                ldsm_x4(bh[np], s2u(&sB_hi[st][row][col]));
                ldsm_x4(bl[np], s2u(&sB_lo[st][row][col]));
            }
            #pragma unroll
            for (int nt = 0; nt < 4; ++nt) {
                const uint32_t* bhp = &bh[nt >> 1][(nt & 1) * 2];
                const uint32_t* blp = &bl[nt >> 1][(nt & 1) * 2];
                mma_bf16(acc[nt], ah, bhp);
                mma_bf16(acc[nt], ah, blp);
                mma_bf16(acc[nt], al, bhp);
            }
        }
    }

    // ---- epilogue: bias + SELU + partial logits ----
    const float kScale = 1.0507009873554805f;
    const float kAlpha = 1.6732632423543772f;
    float pl[2][C_] = {};   // ridx = upper8
    #pragma unroll
    for (int nt = 0; nt < 4; ++nt) {
        #pragma unroll
        for (int e = 0; e < 4; ++e) {
            int col = warp_n * 32 + nt * 8 + (lane & 3) * 2 + (e & 1);
            float x = acc[nt][e] + sBias[col];
            float y = (x > 0.0f) ? x : kAlpha * expm1f(x);
            float h = kScale * y;
            int ridx = e >> 1;
            #pragma unroll
            for (int c = 0; c < C_; ++c)
                pl[ridx][c] = fmaf(h, sWo[col * C_ + c], pl[ridx][c]);
        }
    }
    #pragma unroll
    for (int ridx = 0; ridx < 2; ++ridx)
        #pragma unroll
        for (int c = 0; c < C_; ++c) {
            pl[ridx][c] += __shfl_xor_sync(0xFFFFFFFFu, pl[ridx][c], 1);
            pl[ridx][c] += __shfl_xor_sync(0xFFFFFFFFu, pl[ridx][c], 2);
        }
    if ((lane & 3) == 0) {
        const int slot = blockIdx.x * 2 + warp_n;
        #pragma unroll
        for (int ridx = 0; ridx < 2; ++ridx) {
            int row = m0 + warp_m * 16 + (lane >> 2) + ridx * 8;
            float* dst = g_partial + ((size_t)slot * NSEG + row) * C_;
            #pragma unroll
            for (int c = 0; c < C_; ++c) dst[c] = pl[ridx][c];
        }
    }
}

// ---------------------------------------------------------------------------
// Kernel 3: reduce 24 partial slots + b_o, softmax.  grid=4, block=256.
// ---------------------------------------------------------------------------
__global__ __launch_bounds__(256) void softmax_kernel(
    const float* __restrict__ bo, float* __restrict__ out) {
    int row = blockIdx.x * 256 + threadIdx.x;
    float l[C_];
    #pragma unroll
    for (int c = 0; c < C_; ++c) l[c] = bo[c];
    #pragma unroll
    for (int t = 0; t < NTILE_P; ++t) {
        const float* p = g_partial + ((size_t)t * NSEG + row) * C_;
        #pragma unroll
        for (int c = 0; c < C_; ++c) l[c] += p[c];
    }
    float mx = -INFINITY;
    #pragma unroll
    for (int c = 0; c < C_; ++c) mx = fmaxf(mx, l[c]);
    float sum = 0.0f;
    #pragma unroll
    for (int c = 0; c < C_; ++c) { l[c] = expf(l[c] - mx); sum += l[c]; }
    float inv = 1.0f / sum;
    #pragma unroll
    for (int c = 0; c < C_; ++c) out[(size_t)row * C_ + c] = l[c] * inv;
}

// ---------------------------------------------------------------------------
// Launch
// ---------------------------------------------------------------------------
extern "C" void kernel_launch(void* const* d_in, const int* in_sizes, int n_in,
                              void* d_out, int out_size) {
    const float* hidden = (const float*)d_in[0];
    const int*   seg    = (const int*)d_in[1];
    int base = (n_in >= 7) ? 3 : 2;
    const float* W_h = (const float*)d_in[base + 0];
    const float* b_h = (const float*)d_in[base + 1];
    const float* W_o = (const float*)d_in[base + 2];
    const float* b_o = (const float*)d_in[base + 3];
    float* out = (float*)d_out;

    prep_kernel<<<NSEG + NWPREP, 384>>>(hidden, seg, W_h);

    dim3 gg(NTILE_N, NTILE_M);   // (12, 16) = 192 CTAs
    gemm_fused_kernel<<<gg, 256>>>(b_h, W_o);

    softmax_kernel<<<NSEG / 256, 256>>>(b_o, out);
}

// round 7
// speedup vs baseline: 1.2893x; 1.2893x over previous
#include <cuda_runtime.h>
#include <cuda_bf16.h>
#include <math.h>
#include <stdint.h>

// Problem constants (fixed-shape problem)
#define B_  64
#define S_  512
#define H_  768
#define U_  16
#define C_  5
#define NSEG (B_ * U_)       // 1024
#define NTILE_N 12           // 768 / 64
#define NTILE_M 16           // 1024 / 64
#define NTILE_P (NTILE_N * 2)  // 24 partial slots (32-col warp slices)
#define NWPREP  576          // 24 x 24 transpose blocks

// ---------------------------------------------------------------------------
// Scratch (no allocation allowed)
// ---------------------------------------------------------------------------
__device__ __align__(16) __nv_bfloat16 g_mean_hi[NSEG * H_];
__device__ __align__(16) __nv_bfloat16 g_mean_lo[NSEG * H_];
__device__ __align__(16) __nv_bfloat16 g_wt_hi[H_ * H_];   // W_h^T: [n][k]
__device__ __align__(16) __nv_bfloat16 g_wt_lo[H_ * H_];
__device__ float g_partial[NTILE_P * NSEG * C_];

// ---------------------------------------------------------------------------
// PTX helpers (baseline PTX only — compiles for compute_103)
// ---------------------------------------------------------------------------
__device__ __forceinline__ void mma_bf16(float* c, const uint32_t* a,
                                         const uint32_t* b) {
    asm volatile(
        "mma.sync.aligned.m16n8k16.row.col.f32.bf16.bf16.f32 "
        "{%0,%1,%2,%3}, {%4,%5,%6,%7}, {%8,%9}, {%0,%1,%2,%3};\n"
        : "+f"(c[0]), "+f"(c[1]), "+f"(c[2]), "+f"(c[3])
        : "r"(a[0]), "r"(a[1]), "r"(a[2]), "r"(a[3]), "r"(b[0]), "r"(b[1]));
}
__device__ __forceinline__ void ldsm_x4(uint32_t* r, uint32_t addr) {
    asm volatile(
        "ldmatrix.sync.aligned.m8n8.x4.shared.b16 {%0,%1,%2,%3}, [%4];"
        : "=r"(r[0]), "=r"(r[1]), "=r"(r[2]), "=r"(r[3]) : "r"(addr));
}
#define CP16(dst, src) \
    asm volatile("cp.async.cg.shared.global [%0], [%1], 16;" \
                 :: "r"(dst), "l"(src))
__device__ __forceinline__ uint32_t s2u(const void* p) {
    return (uint32_t)__cvta_generic_to_shared(p);
}

// ---------------------------------------------------------------------------
// Kernel 1 (merged prep), block = 384:
//   blocks [0, NSEG): segment count + mean (2 row-groups x 4 chains) + split
//   blocks [NSEG, NSEG+NWPREP): W_h transpose + bf16 split (tid<256 active)
// ---------------------------------------------------------------------------
__global__ __launch_bounds__(384) void prep_kernel(
    const float* __restrict__ hidden, const int* __restrict__ seg,
    const float* __restrict__ W) {
    const int bid = blockIdx.x;
    const int tid = threadIdx.x;

    if (bid < NSEG) {
        // ---- per-segment count: 128 threads, int4 loads ----
        __shared__ int s_lt, s_eq;
        __shared__ float4 red[192];
        const int b = bid >> 4, u = bid & 15;
        if (tid == 0) { s_lt = 0; s_eq = 0; }
        __syncthreads();
        if (tid < 128) {
            int4 v = ((const int4*)(seg + (size_t)b * S_))[tid];
            int lt = (v.x < u) + (v.y < u) + (v.z < u) + (v.w < u);
            int eq = (v.x == u) + (v.y == u) + (v.z == u) + (v.w == u);
            #pragma unroll
            for (int off = 16; off > 0; off >>= 1) {
                lt += __shfl_xor_sync(0xFFFFFFFFu, lt, off);
                eq += __shfl_xor_sync(0xFFFFFFFFu, eq, off);
            }
            if ((tid & 31) == 0) { atomicAdd(&s_lt, lt); atomicAdd(&s_eq, eq); }
        }
        __syncthreads();
        const int start = b * S_ + s_lt;
        const int cnt   = s_eq;
        const float inv = 1.0f / fmaxf((float)cnt, 1.0f);

        // ---- mean: 2 row-groups x 192 cols, 4 accumulator chains each ----
        const int gcol = tid % 192;
        const int grp  = tid / 192;   // 0 or 1
        const float4* __restrict__ hp =
            (const float4*)hidden + (size_t)start * (H_ / 4) + gcol;

        float4 a0 = {0,0,0,0}, a1 = {0,0,0,0}, a2 = {0,0,0,0}, a3 = {0,0,0,0};
        int r = grp;                    // group 0: even rows; group 1: odd
        for (; r + 6 < cnt; r += 8) {
            float4 v0 = hp[(size_t)(r + 0) * (H_ / 4)];
            float4 v1 = hp[(size_t)(r + 2) * (H_ / 4)];
            float4 v2 = hp[(size_t)(r + 4) * (H_ / 4)];
            float4 v3 = hp[(size_t)(r + 6) * (H_ / 4)];
            a0.x += v0.x; a0.y += v0.y; a0.z += v0.z; a0.w += v0.w;
            a1.x += v1.x; a1.y += v1.y; a1.z += v1.z; a1.w += v1.w;
            a2.x += v2.x; a2.y += v2.y; a2.z += v2.z; a2.w += v2.w;
            a3.x += v3.x; a3.y += v3.y; a3.z += v3.z; a3.w += v3.w;
        }
        for (; r < cnt; r += 2) {
            float4 v0 = hp[(size_t)r * (H_ / 4)];
            a0.x += v0.x; a0.y += v0.y; a0.z += v0.z; a0.w += v0.w;
        }
        a0.x = (a0.x + a1.x) + (a2.x + a3.x);
        a0.y = (a0.y + a1.y) + (a2.y + a3.y);
        a0.z = (a0.z + a1.z) + (a2.z + a3.z);
        a0.w = (a0.w + a1.w) + (a2.w + a3.w);

        if (grp == 1) red[gcol] = a0;
        __syncthreads();
        if (grp == 0) {
            float4 p = red[gcol];
            float m[4];
            m[0] = (a0.x + p.x) * inv;
            m[1] = (a0.y + p.y) * inv;
            m[2] = (a0.z + p.z) * inv;
            m[3] = (a0.w + p.w) * inv;

            __nv_bfloat16 hi[4], lo[4];
            #pragma unroll
            for (int i = 0; i < 4; ++i) {
                hi[i] = __float2bfloat16(m[i]);
                lo[i] = __float2bfloat16(m[i] - __bfloat162float(hi[i]));
            }
            __nv_bfloat162 ph0 = {hi[0], hi[1]}, ph1 = {hi[2], hi[3]};
            __nv_bfloat162 pl0 = {lo[0], lo[1]}, pl1 = {lo[2], lo[3]};
            uint2 uh, ul;
            uh.x = *(uint32_t*)&ph0; uh.y = *(uint32_t*)&ph1;
            ul.x = *(uint32_t*)&pl0; ul.y = *(uint32_t*)&pl1;
            ((uint2*)g_mean_hi)[(size_t)bid * (H_ / 4) + gcol] = uh;
            ((uint2*)g_mean_lo)[(size_t)bid * (H_ / 4) + gcol] = ul;
        }
    } else {
        // ---- W_h transpose + split (256 active threads) ----
        __shared__ float t[32][33];
        const int w  = bid - NSEG;
        const int n0 = (w % 24) * 32, k0 = (w / 24) * 32;
        if (tid < 256) {
            const int tx = tid & 31, ty = tid >> 5;   // 32 x 8
            #pragma unroll
            for (int r = 0; r < 32; r += 8)
                t[ty + r][tx] = W[(size_t)(k0 + ty + r) * H_ + n0 + tx];
        }
        __syncthreads();
        if (tid < 256) {
            const int tx = tid & 31, ty = tid >> 5;
            const int k = k0 + tx;
            #pragma unroll
            for (int r = 0; r < 32; r += 8) {
                const int n = n0 + ty + r;
                float v = t[tx][ty + r];
                __nv_bfloat16 hi = __float2bfloat16(v);
                __nv_bfloat16 lo = __float2bfloat16(v - __bfloat162float(hi));
                g_wt_hi[(size_t)n * H_ + k] = hi;
                g_wt_lo[(size_t)n * H_ + k] = lo;
            }
        }
    }
}

// ---------------------------------------------------------------------------
// Kernel 2: bf16x3 warp-MMA GEMM + bias + SELU + fused partial logits.
// (Round-5 proven config.)
// CTA tile 64x64, block = 128 (4 warps: 2M x 2N, warp tile 32x32).
// K chunks of 32, 2-stage cp.async pipeline, ldmatrix fragment loads.
// grid = (12, 16) = 192 CTAs.
// ---------------------------------------------------------------------------
#define TM 64
#define TN 64
#define KC 32
#define KPAD 40
#define NCHUNK (H_ / KC)   // 24

__global__ __launch_bounds__(128) void gemm_fused_kernel(
    const float* __restrict__ bias, const float* __restrict__ Wo) {
    __shared__ __align__(16) __nv_bfloat16 sA_hi[2][TM][KPAD];
    __shared__ __align__(16) __nv_bfloat16 sA_lo[2][TM][KPAD];
    __shared__ __align__(16) __nv_bfloat16 sB_hi[2][TN][KPAD];
    __shared__ __align__(16) __nv_bfloat16 sB_lo[2][TN][KPAD];
    __shared__ float sWo[TN * C_];
    __shared__ float sBias[TN];

    const int tid  = threadIdx.x;
    const int wid  = tid >> 5;
    const int lane = tid & 31;
    const int warp_m = wid & 1;
    const int warp_n = wid >> 1;
    const int n0 = blockIdx.x * TN;
    const int m0 = blockIdx.y * TM;

    for (int i = tid; i < TN * C_; i += 128) sWo[i] = Wo[(size_t)n0 * C_ + i];
    if (tid < TN) sBias[tid] = bias[n0 + tid];

    const __nv_bfloat16* __restrict__ Ahi = g_mean_hi + (size_t)m0 * H_;
    const __nv_bfloat16* __restrict__ Alo = g_mean_lo + (size_t)m0 * H_;
    const __nv_bfloat16* __restrict__ Bhi = g_wt_hi + (size_t)n0 * H_;
    const __nv_bfloat16* __restrict__ Blo = g_wt_lo + (size_t)n0 * H_;

    // per-thread copy coords: 256 16B-units per array, 2 per thread
    const int row_c0 = tid >> 2,          u_c0 = (tid & 3);
    const int row_c1 = (tid + 128) >> 2,  u_c1 = ((tid + 128) & 3);

    auto issue = [&](int st, int k0) {
        CP16(s2u(&sA_hi[st][row_c0][u_c0 * 8]),
             Ahi + (size_t)row_c0 * H_ + k0 + u_c0 * 8);
        CP16(s2u(&sA_hi[st][row_c1][u_c1 * 8]),
             Ahi + (size_t)row_c1 * H_ + k0 + u_c1 * 8);
        CP16(s2u(&sA_lo[st][row_c0][u_c0 * 8]),
             Alo + (size_t)row_c0 * H_ + k0 + u_c0 * 8);
        CP16(s2u(&sA_lo[st][row_c1][u_c1 * 8]),
             Alo + (size_t)row_c1 * H_ + k0 + u_c1 * 8);
        CP16(s2u(&sB_hi[st][row_c0][u_c0 * 8]),
             Bhi + (size_t)row_c0 * H_ + k0 + u_c0 * 8);
        CP16(s2u(&sB_hi[st][row_c1][u_c1 * 8]),
             Bhi + (size_t)row_c1 * H_ + k0 + u_c1 * 8);
        CP16(s2u(&sB_lo[st][row_c0][u_c0 * 8]),
             Blo + (size_t)row_c0 * H_ + k0 + u_c0 * 8);
        CP16(s2u(&sB_lo[st][row_c1][u_c1 * 8]),
             Blo + (size_t)row_c1 * H_ + k0 + u_c1 * 8);
    };

    issue(0, 0);
    asm volatile("cp.async.commit_group;" ::: "memory");

    float acc[2][4][4] = {};

    for (int ck = 0; ck < NCHUNK; ++ck) {
        asm volatile("cp.async.wait_group 0;" ::: "memory");
        __syncthreads();
        if (ck + 1 < NCHUNK) issue((ck + 1) & 1, (ck + 1) * KC);
        asm volatile("cp.async.commit_group;" ::: "memory");

        const int st = ck & 1;
        #pragma unroll
        for (int ks = 0; ks < 2; ++ks) {
            const int kw = ks * 16;
            uint32_t ah[2][4], al[2][4], bh[2][4], bl[2][4];
            #pragma unroll
            for (int mt = 0; mt < 2; ++mt) {
                int row = warp_m * 32 + mt * 16 + (lane & 15);
                int col = kw + ((lane >> 4) << 3);
                ldsm_x4(ah[mt], s2u(&sA_hi[st][row][col]));
                ldsm_x4(al[mt], s2u(&sA_lo[st][row][col]));
            }
            #pragma unroll
            for (int np = 0; np < 2; ++np) {
                int row = warp_n * 32 + np * 16 + (lane & 7) +
                          ((lane >> 4) << 3);
                int col = kw + (((lane >> 3) & 1) << 3);
                ldsm_x4(bh[np], s2u(&sB_hi[st][row][col]));
                ldsm_x4(bl[np], s2u(&sB_lo[st][row][col]));
            }
            #pragma unroll
            for (int mt = 0; mt < 2; ++mt) {
                #pragma unroll
                for (int nt = 0; nt < 4; ++nt) {
                    const uint32_t* bhp = &bh[nt >> 1][(nt & 1) * 2];
                    const uint32_t* blp = &bl[nt >> 1][(nt & 1) * 2];
                    mma_bf16(acc[mt][nt], ah[mt], bhp);
                    mma_bf16(acc[mt][nt], ah[mt], blp);
                    mma_bf16(acc[mt][nt], al[mt], bhp);
                }
            }
        }
    }

    // ---- epilogue: bias + SELU + partial logits ----
    const float kScale = 1.0507009873554805f;
    const float kAlpha = 1.6732632423543772f;
    float pl[4][C_] = {};   // ridx = mt*2 + upper8
    #pragma unroll
    for (int mt = 0; mt < 2; ++mt) {
        #pragma unroll
        for (int nt = 0; nt < 4; ++nt) {
            #pragma unroll
            for (int e = 0; e < 4; ++e) {
                int col = warp_n * 32 + nt * 8 + (lane & 3) * 2 + (e & 1);
                float x = acc[mt][nt][e] + sBias[col];
                float y = (x > 0.0f) ? x : kAlpha * expm1f(x);
                float h = kScale * y;
                int ridx = mt * 2 + (e >> 1);
                #pragma unroll
                for (int c = 0; c < C_; ++c)
                    pl[ridx][c] = fmaf(h, sWo[col * C_ + c], pl[ridx][c]);
            }
        }
    }
    #pragma unroll
    for (int ridx = 0; ridx < 4; ++ridx)
        #pragma unroll
        for (int c = 0; c < C_; ++c) {
            pl[ridx][c] += __shfl_xor_sync(0xFFFFFFFFu, pl[ridx][c], 1);
            pl[ridx][c] += __shfl_xor_sync(0xFFFFFFFFu, pl[ridx][c], 2);
        }
    if ((lane & 3) == 0) {
        const int slot = blockIdx.x * 2 + warp_n;
        #pragma unroll
        for (int ridx = 0; ridx < 4; ++ridx) {
            int row = m0 + warp_m * 32 + (ridx >> 1) * 16 + (lane >> 2) +
                      (ridx & 1) * 8;
            float* dst = g_partial + ((size_t)slot * NSEG + row) * C_;
            #pragma unroll
            for (int c = 0; c < C_; ++c) dst[c] = pl[ridx][c];
        }
    }
}

// ---------------------------------------------------------------------------
// Kernel 3: reduce 24 partial slots + b_o, softmax.  grid=4, block=256.
// ---------------------------------------------------------------------------
__global__ __launch_bounds__(256) void softmax_kernel(
    const float* __restrict__ bo, float* __restrict__ out) {
    int row = blockIdx.x * 256 + threadIdx.x;
    float l[C_];
    #pragma unroll
    for (int c = 0; c < C_; ++c) l[c] = bo[c];
    #pragma unroll
    for (int t = 0; t < NTILE_P; ++t) {
        const float* p = g_partial + ((size_t)t * NSEG + row) * C_;
        #pragma unroll
        for (int c = 0; c < C_; ++c) l[c] += p[c];
    }
    float mx = -INFINITY;
    #pragma unroll
    for (int c = 0; c < C_; ++c) mx = fmaxf(mx, l[c]);
    float sum = 0.0f;
    #pragma unroll
    for (int c = 0; c < C_; ++c) { l[c] = expf(l[c] - mx); sum += l[c]; }
    float inv = 1.0f / sum;
    #pragma unroll
    for (int c = 0; c < C_; ++c) out[(size_t)row * C_ + c] = l[c] * inv;
}

// ---------------------------------------------------------------------------
// Launch
// ---------------------------------------------------------------------------
extern "C" void kernel_launch(void* const* d_in, const int* in_sizes, int n_in,
                              void* d_out, int out_size) {
    const float* hidden = (const float*)d_in[0];
    const int*   seg    = (const int*)d_in[1];
    int base = (n_in >= 7) ? 3 : 2;
    const float* W_h = (const float*)d_in[base + 0];
    const float* b_h = (const float*)d_in[base + 1];
    const float* W_o = (const float*)d_in[base + 2];
    const float* b_o = (const float*)d_in[base + 3];
    float* out = (float*)d_out;

    prep_kernel<<<NSEG + NWPREP, 384>>>(hidden, seg, W_h);

    dim3 gg(NTILE_N, NTILE_M);   // (12, 16) = 192 CTAs
    gemm_fused_kernel<<<gg, 128>>>(b_h, W_o);

    softmax_kernel<<<NSEG / 256, 256>>>(b_o, out);
}

// round 8
// speedup vs baseline: 1.3436x; 1.0421x over previous
#include <cuda_runtime.h>
#include <cuda_bf16.h>
#include <math.h>
#include <stdint.h>

// Problem constants (fixed-shape problem)
#define B_  64
#define S_  512
#define H_  768
#define U_  16
#define C_  5
#define NSEG (B_ * U_)       // 1024
#define NTILE_N 12           // 768 / 64
#define NTILE_M 16           // 1024 / 64
#define NTILE_P (NTILE_N * 2)  // 24 partial slots (32-col warp slices)
#define NWPREP  576          // 24 x 24 transpose blocks

// ---------------------------------------------------------------------------
// Scratch (no allocation allowed)
// ---------------------------------------------------------------------------
__device__ __align__(16) __nv_bfloat16 g_mean_hi[NSEG * H_];
__device__ __align__(16) __nv_bfloat16 g_mean_lo[NSEG * H_];
__device__ __align__(16) __nv_bfloat16 g_wt_hi[H_ * H_];   // W_h^T: [n][k]
__device__ __align__(16) __nv_bfloat16 g_wt_lo[H_ * H_];
__device__ float g_partial[NTILE_P * NSEG * C_];

// ---------------------------------------------------------------------------
// PTX helpers (baseline PTX only — compiles for compute_103)
// ---------------------------------------------------------------------------
__device__ __forceinline__ void mma_bf16(float* c, const uint32_t* a,
                                         const uint32_t* b) {
    asm volatile(
        "mma.sync.aligned.m16n8k16.row.col.f32.bf16.bf16.f32 "
        "{%0,%1,%2,%3}, {%4,%5,%6,%7}, {%8,%9}, {%0,%1,%2,%3};\n"
        : "+f"(c[0]), "+f"(c[1]), "+f"(c[2]), "+f"(c[3])
        : "r"(a[0]), "r"(a[1]), "r"(a[2]), "r"(a[3]), "r"(b[0]), "r"(b[1]));
}
__device__ __forceinline__ void ldsm_x4(uint32_t* r, uint32_t addr) {
    asm volatile(
        "ldmatrix.sync.aligned.m8n8.x4.shared.b16 {%0,%1,%2,%3}, [%4];"
        : "=r"(r[0]), "=r"(r[1]), "=r"(r[2]), "=r"(r[3]) : "r"(addr));
}
#define CP16(dst, src) \
    asm volatile("cp.async.cg.shared.global [%0], [%1], 16;" \
                 :: "r"(dst), "l"(src))
__device__ __forceinline__ uint32_t s2u(const void* p) {
    return (uint32_t)__cvta_generic_to_shared(p);
}

// ---------------------------------------------------------------------------
// Kernel 1 (merged prep), block = 384 — unchanged from round 7 (proven).
// ---------------------------------------------------------------------------
__global__ __launch_bounds__(384) void prep_kernel(
    const float* __restrict__ hidden, const int* __restrict__ seg,
    const float* __restrict__ W) {
    const int bid = blockIdx.x;
    const int tid = threadIdx.x;

    if (bid < NSEG) {
        __shared__ int s_lt, s_eq;
        __shared__ float4 red[192];
        const int b = bid >> 4, u = bid & 15;
        if (tid == 0) { s_lt = 0; s_eq = 0; }
        __syncthreads();
        if (tid < 128) {
            int4 v = ((const int4*)(seg + (size_t)b * S_))[tid];
            int lt = (v.x < u) + (v.y < u) + (v.z < u) + (v.w < u);
            int eq = (v.x == u) + (v.y == u) + (v.z == u) + (v.w == u);
            #pragma unroll
            for (int off = 16; off > 0; off >>= 1) {
                lt += __shfl_xor_sync(0xFFFFFFFFu, lt, off);
                eq += __shfl_xor_sync(0xFFFFFFFFu, eq, off);
            }
            if ((tid & 31) == 0) { atomicAdd(&s_lt, lt); atomicAdd(&s_eq, eq); }
        }
        __syncthreads();
        const int start = b * S_ + s_lt;
        const int cnt   = s_eq;
        const float inv = 1.0f / fmaxf((float)cnt, 1.0f);

        const int gcol = tid % 192;
        const int grp  = tid / 192;
        const float4* __restrict__ hp =
            (const float4*)hidden + (size_t)start * (H_ / 4) + gcol;

        float4 a0 = {0,0,0,0}, a1 = {0,0,0,0}, a2 = {0,0,0,0}, a3 = {0,0,0,0};
        int r = grp;
        for (; r + 6 < cnt; r += 8) {
            float4 v0 = hp[(size_t)(r + 0) * (H_ / 4)];
            float4 v1 = hp[(size_t)(r + 2) * (H_ / 4)];
            float4 v2 = hp[(size_t)(r + 4) * (H_ / 4)];
            float4 v3 = hp[(size_t)(r + 6) * (H_ / 4)];
            a0.x += v0.x; a0.y += v0.y; a0.z += v0.z; a0.w += v0.w;
            a1.x += v1.x; a1.y += v1.y; a1.z += v1.z; a1.w += v1.w;
            a2.x += v2.x; a2.y += v2.y; a2.z += v2.z; a2.w += v2.w;
            a3.x += v3.x; a3.y += v3.y; a3.z += v3.z; a3.w += v3.w;
        }
        for (; r < cnt; r += 2) {
            float4 v0 = hp[(size_t)r * (H_ / 4)];
            a0.x += v0.x; a0.y += v0.y; a0.z += v0.z; a0.w += v0.w;
        }
        a0.x = (a0.x + a1.x) + (a2.x + a3.x);
        a0.y = (a0.y + a1.y) + (a2.y + a3.y);
        a0.z = (a0.z + a1.z) + (a2.z + a3.z);
        a0.w = (a0.w + a1.w) + (a2.w + a3.w);

        if (grp == 1) red[gcol] = a0;
        __syncthreads();
        if (grp == 0) {
            float4 p = red[gcol];
            float m[4];
            m[0] = (a0.x + p.x) * inv;
            m[1] = (a0.y + p.y) * inv;
            m[2] = (a0.z + p.z) * inv;
            m[3] = (a0.w + p.w) * inv;

            __nv_bfloat16 hi[4], lo[4];
            #pragma unroll
            for (int i = 0; i < 4; ++i) {
                hi[i] = __float2bfloat16(m[i]);
                lo[i] = __float2bfloat16(m[i] - __bfloat162float(hi[i]));
            }
            __nv_bfloat162 ph0 = {hi[0], hi[1]}, ph1 = {hi[2], hi[3]};
            __nv_bfloat162 pl0 = {lo[0], lo[1]}, pl1 = {lo[2], lo[3]};
            uint2 uh, ul;
            uh.x = *(uint32_t*)&ph0; uh.y = *(uint32_t*)&ph1;
            ul.x = *(uint32_t*)&pl0; ul.y = *(uint32_t*)&pl1;
            ((uint2*)g_mean_hi)[(size_t)bid * (H_ / 4) + gcol] = uh;
            ((uint2*)g_mean_lo)[(size_t)bid * (H_ / 4) + gcol] = ul;
        }
    } else {
        __shared__ float t[32][33];
        const int w  = bid - NSEG;
        const int n0 = (w % 24) * 32, k0 = (w / 24) * 32;
        if (tid < 256) {
            const int tx = tid & 31, ty = tid >> 5;
            #pragma unroll
            for (int r = 0; r < 32; r += 8)
                t[ty + r][tx] = W[(size_t)(k0 + ty + r) * H_ + n0 + tx];
        }
        __syncthreads();
        if (tid < 256) {
            const int tx = tid & 31, ty = tid >> 5;
            const int k = k0 + tx;
            #pragma unroll
            for (int r = 0; r < 32; r += 8) {
                const int n = n0 + ty + r;
                float v = t[tx][ty + r];
                __nv_bfloat16 hi = __float2bfloat16(v);
                __nv_bfloat16 lo = __float2bfloat16(v - __bfloat162float(hi));
                g_wt_hi[(size_t)n * H_ + k] = hi;
                g_wt_lo[(size_t)n * H_ + k] = lo;
            }
        }
    }
}

// ---------------------------------------------------------------------------
// Kernel 2: bf16x3 warp-MMA GEMM + bias + SELU + fused partial logits.
// CTA tile 64x64, block = 128 (4 warps: 2M x 2N, warp tile 32x32).
// K chunks of 64 (12 iterations), 2-stage cp.async pipeline (dynamic smem),
// ldmatrix fragment loads.  grid = (12, 16) = 192 CTAs.
// ---------------------------------------------------------------------------
#define TM 64
#define TN 64
#define KC 64
#define KPAD 72
#define NCHUNK (H_ / KC)   // 12
#define STAGE_ELEMS (64 * KPAD)            // per array per stage
#define SMEM_BYTES (4 * 2 * STAGE_ELEMS * 2 + TN * C_ * 4 + TN * 4)

__global__ __launch_bounds__(128) void gemm_fused_kernel(
    const float* __restrict__ bias, const float* __restrict__ Wo) {
    extern __shared__ __align__(16) char dynsmem[];
    __nv_bfloat16* sA_hi = (__nv_bfloat16*)dynsmem;         // [2][64][KPAD]
    __nv_bfloat16* sA_lo = sA_hi + 2 * STAGE_ELEMS;
    __nv_bfloat16* sB_hi = sA_lo + 2 * STAGE_ELEMS;
    __nv_bfloat16* sB_lo = sB_hi + 2 * STAGE_ELEMS;
    float* sWo   = (float*)(sB_lo + 2 * STAGE_ELEMS);
    float* sBias = sWo + TN * C_;

    const int tid  = threadIdx.x;
    const int wid  = tid >> 5;
    const int lane = tid & 31;
    const int warp_m = wid & 1;
    const int warp_n = wid >> 1;
    const int n0 = blockIdx.x * TN;
    const int m0 = blockIdx.y * TM;

    for (int i = tid; i < TN * C_; i += 128) sWo[i] = Wo[(size_t)n0 * C_ + i];
    if (tid < TN) sBias[tid] = bias[n0 + tid];

    const __nv_bfloat16* __restrict__ Ahi = g_mean_hi + (size_t)m0 * H_;
    const __nv_bfloat16* __restrict__ Alo = g_mean_lo + (size_t)m0 * H_;
    const __nv_bfloat16* __restrict__ Bhi = g_wt_hi + (size_t)n0 * H_;
    const __nv_bfloat16* __restrict__ Blo = g_wt_lo + (size_t)n0 * H_;

    // copy: per array per stage = 64 rows x 8 16B-units = 512 units;
    // 128 threads x 4 units each.
    auto issue = [&](int st, int k0) {
        #pragma unroll
        for (int i = 0; i < 4; ++i) {
            const int unit = tid + i * 128;
            const int row = unit >> 3, u = unit & 7;
            const size_t goff = (size_t)row * H_ + k0 + u * 8;
            const int soff = (st * 64 + row) * KPAD + u * 8;
            CP16(s2u(sA_hi + soff), Ahi + goff);
            CP16(s2u(sA_lo + soff), Alo + goff);
            CP16(s2u(sB_hi + soff), Bhi + goff);
            CP16(s2u(sB_lo + soff), Blo + goff);
        }
    };

    issue(0, 0);
    asm volatile("cp.async.commit_group;" ::: "memory");

    float acc[2][4][4] = {};

    for (int ck = 0; ck < NCHUNK; ++ck) {
        asm volatile("cp.async.wait_group 0;" ::: "memory");
        __syncthreads();
        if (ck + 1 < NCHUNK) issue((ck + 1) & 1, (ck + 1) * KC);
        asm volatile("cp.async.commit_group;" ::: "memory");

        const int st = ck & 1;
        const int sbase = st * 64 * KPAD;
        #pragma unroll
        for (int ks = 0; ks < KC / 16; ++ks) {
            const int kw = ks * 16;
            uint32_t ah[2][4], al[2][4], bh[2][4], bl[2][4];
            #pragma unroll
            for (int mt = 0; mt < 2; ++mt) {
                int row = warp_m * 32 + mt * 16 + (lane & 15);
                int col = kw + ((lane >> 4) << 3);
                ldsm_x4(ah[mt], s2u(sA_hi + sbase + row * KPAD + col));
                ldsm_x4(al[mt], s2u(sA_lo + sbase + row * KPAD + col));
            }
            #pragma unroll
            for (int np = 0; np < 2; ++np) {
                int row = warp_n * 32 + np * 16 + (lane & 7) +
                          ((lane >> 4) << 3);
                int col = kw + (((lane >> 3) & 1) << 3);
                ldsm_x4(bh[np], s2u(sB_hi + sbase + row * KPAD + col));
                ldsm_x4(bl[np], s2u(sB_lo + sbase + row * KPAD + col));
            }
            #pragma unroll
            for (int mt = 0; mt < 2; ++mt) {
                #pragma unroll
                for (int nt = 0; nt < 4; ++nt) {
                    const uint32_t* bhp = &bh[nt >> 1][(nt & 1) * 2];
                    const uint32_t* blp = &bl[nt >> 1][(nt & 1) * 2];
                    mma_bf16(acc[mt][nt], ah[mt], bhp);
                    mma_bf16(acc[mt][nt], ah[mt], blp);
                    mma_bf16(acc[mt][nt], al[mt], bhp);
                }
            }
        }
    }

    // ---- epilogue: bias + SELU + partial logits ----
    const float kScale = 1.0507009873554805f;
    const float kAlpha = 1.6732632423543772f;
    float pl[4][C_] = {};
    #pragma unroll
    for (int mt = 0; mt < 2; ++mt) {
        #pragma unroll
        for (int nt = 0; nt < 4; ++nt) {
            #pragma unroll
            for (int e = 0; e < 4; ++e) {
                int col = warp_n * 32 + nt * 8 + (lane & 3) * 2 + (e & 1);
                float x = acc[mt][nt][e] + sBias[col];
                float y = (x > 0.0f) ? x : kAlpha * expm1f(x);
                float h = kScale * y;
                int ridx = mt * 2 + (e >> 1);
                #pragma unroll
                for (int c = 0; c < C_; ++c)
                    pl[ridx][c] = fmaf(h, sWo[col * C_ + c], pl[ridx][c]);
            }
        }
    }
    #pragma unroll
    for (int ridx = 0; ridx < 4; ++ridx)
        #pragma unroll
        for (int c = 0; c < C_; ++c) {
            pl[ridx][c] += __shfl_xor_sync(0xFFFFFFFFu, pl[ridx][c], 1);
            pl[ridx][c] += __shfl_xor_sync(0xFFFFFFFFu, pl[ridx][c], 2);
        }
    if ((lane & 3) == 0) {
        const int slot = blockIdx.x * 2 + warp_n;
        #pragma unroll
        for (int ridx = 0; ridx < 4; ++ridx) {
            int row = m0 + warp_m * 32 + (ridx >> 1) * 16 + (lane >> 2) +
                      (ridx & 1) * 8;
            float* dst = g_partial + ((size_t)slot * NSEG + row) * C_;
            #pragma unroll
            for (int c = 0; c < C_; ++c) dst[c] = pl[ridx][c];
        }
    }
}

// ---------------------------------------------------------------------------
// Kernel 3: reduce 24 partial slots + b_o, softmax.  grid=4, block=256.
// ---------------------------------------------------------------------------
__global__ __launch_bounds__(256) void softmax_kernel(
    const float* __restrict__ bo, float* __restrict__ out) {
    int row = blockIdx.x * 256 + threadIdx.x;
    float l[C_];
    #pragma unroll
    for (int c = 0; c < C_; ++c) l[c] = bo[c];
    #pragma unroll
    for (int t = 0; t < NTILE_P; ++t) {
        const float* p = g_partial + ((size_t)t * NSEG + row) * C_;
        #pragma unroll
        for (int c = 0; c < C_; ++c) l[c] += p[c];
    }
    float mx = -INFINITY;
    #pragma unroll
    for (int c = 0; c < C_; ++c) mx = fmaxf(mx, l[c]);
    float sum = 0.0f;
    #pragma unroll
    for (int c = 0; c < C_; ++c) { l[c] = expf(l[c] - mx); sum += l[c]; }
    float inv = 1.0f / sum;
    #pragma unroll
    for (int c = 0; c < C_; ++c) out[(size_t)row * C_ + c] = l[c] * inv;
}

// ---------------------------------------------------------------------------
// Launch
// ---------------------------------------------------------------------------
extern "C" void kernel_launch(void* const* d_in, const int* in_sizes, int n_in,
                              void* d_out, int out_size) {
    const float* hidden = (const float*)d_in[0];
    const int*   seg    = (const int*)d_in[1];
    int base = (n_in >= 7) ? 3 : 2;
    const float* W_h = (const float*)d_in[base + 0];
    const float* b_h = (const float*)d_in[base + 1];
    const float* W_o = (const float*)d_in[base + 2];
    const float* b_o = (const float*)d_in[base + 3];
    float* out = (float*)d_out;

    cudaFuncSetAttribute(gemm_fused_kernel,
                         cudaFuncAttributeMaxDynamicSharedMemorySize,
                         SMEM_BYTES);

    prep_kernel<<<NSEG + NWPREP, 384>>>(hidden, seg, W_h);

    dim3 gg(NTILE_N, NTILE_M);   // (12, 16) = 192 CTAs
    gemm_fused_kernel<<<gg, 128, SMEM_BYTES>>>(b_h, W_o);

    softmax_kernel<<<NSEG / 256, 256>>>(b_o, out);
}

// round 9
// speedup vs baseline: 1.4046x; 1.0454x over previous
#include <cuda_runtime.h>
#include <cuda_bf16.h>
#include <math.h>
#include <stdint.h>

// Problem constants (fixed-shape problem)
#define B_  64
#define S_  512
#define H_  768
#define U_  16
#define C_  5
#define NSEG (B_ * U_)       // 1024
#define NTILE_N 8            // 768 / 96
#define NTILE_M 16           // 1024 / 64
#define NTILE_P (NTILE_N * 2)  // 16 partial slots (48-col warp slices)
#define NWPREP  576          // 24 x 24 transpose blocks

// ---------------------------------------------------------------------------
// Scratch (no allocation allowed)
// ---------------------------------------------------------------------------
__device__ __align__(16) __nv_bfloat16 g_mean_hi[NSEG * H_];
__device__ __align__(16) __nv_bfloat16 g_mean_lo[NSEG * H_];
__device__ __align__(16) __nv_bfloat16 g_wt_hi[H_ * H_];   // W_h^T: [n][k]
__device__ __align__(16) __nv_bfloat16 g_wt_lo[H_ * H_];
__device__ float g_partial[NTILE_P * NSEG * C_];

// ---------------------------------------------------------------------------
// PTX helpers (baseline PTX only — compiles for compute_103)
// ---------------------------------------------------------------------------
__device__ __forceinline__ void mma_bf16(float* c, const uint32_t* a,
                                         const uint32_t* b) {
    asm volatile(
        "mma.sync.aligned.m16n8k16.row.col.f32.bf16.bf16.f32 "
        "{%0,%1,%2,%3}, {%4,%5,%6,%7}, {%8,%9}, {%0,%1,%2,%3};\n"
        : "+f"(c[0]), "+f"(c[1]), "+f"(c[2]), "+f"(c[3])
        : "r"(a[0]), "r"(a[1]), "r"(a[2]), "r"(a[3]), "r"(b[0]), "r"(b[1]));
}
__device__ __forceinline__ void ldsm_x4(uint32_t* r, uint32_t addr) {
    asm volatile(
        "ldmatrix.sync.aligned.m8n8.x4.shared.b16 {%0,%1,%2,%3}, [%4];"
        : "=r"(r[0]), "=r"(r[1]), "=r"(r[2]), "=r"(r[3]) : "r"(addr));
}
#define CP16(dst, src) \
    asm volatile("cp.async.cg.shared.global [%0], [%1], 16;" \
                 :: "r"(dst), "l"(src))
__device__ __forceinline__ uint32_t s2u(const void* p) {
    return (uint32_t)__cvta_generic_to_shared(p);
}

// ---------------------------------------------------------------------------
// Kernel 1 (merged prep), block = 384 — unchanged (proven).
// ---------------------------------------------------------------------------
__global__ __launch_bounds__(384) void prep_kernel(
    const float* __restrict__ hidden, const int* __restrict__ seg,
    const float* __restrict__ W) {
    const int bid = blockIdx.x;
    const int tid = threadIdx.x;

    if (bid < NSEG) {
        __shared__ int s_lt, s_eq;
        __shared__ float4 red[192];
        const int b = bid >> 4, u = bid & 15;
        if (tid == 0) { s_lt = 0; s_eq = 0; }
        __syncthreads();
        if (tid < 128) {
            int4 v = ((const int4*)(seg + (size_t)b * S_))[tid];
            int lt = (v.x < u) + (v.y < u) + (v.z < u) + (v.w < u);
            int eq = (v.x == u) + (v.y == u) + (v.z == u) + (v.w == u);
            #pragma unroll
            for (int off = 16; off > 0; off >>= 1) {
                lt += __shfl_xor_sync(0xFFFFFFFFu, lt, off);
                eq += __shfl_xor_sync(0xFFFFFFFFu, eq, off);
            }
            if ((tid & 31) == 0) { atomicAdd(&s_lt, lt); atomicAdd(&s_eq, eq); }
        }
        __syncthreads();
        const int start = b * S_ + s_lt;
        const int cnt   = s_eq;
        const float inv = 1.0f / fmaxf((float)cnt, 1.0f);

        const int gcol = tid % 192;
        const int grp  = tid / 192;
        const float4* __restrict__ hp =
            (const float4*)hidden + (size_t)start * (H_ / 4) + gcol;

        float4 a0 = {0,0,0,0}, a1 = {0,0,0,0}, a2 = {0,0,0,0}, a3 = {0,0,0,0};
        int r = grp;
        for (; r + 6 < cnt; r += 8) {
            float4 v0 = hp[(size_t)(r + 0) * (H_ / 4)];
            float4 v1 = hp[(size_t)(r + 2) * (H_ / 4)];
            float4 v2 = hp[(size_t)(r + 4) * (H_ / 4)];
            float4 v3 = hp[(size_t)(r + 6) * (H_ / 4)];
            a0.x += v0.x; a0.y += v0.y; a0.z += v0.z; a0.w += v0.w;
            a1.x += v1.x; a1.y += v1.y; a1.z += v1.z; a1.w += v1.w;
            a2.x += v2.x; a2.y += v2.y; a2.z += v2.z; a2.w += v2.w;
            a3.x += v3.x; a3.y += v3.y; a3.z += v3.z; a3.w += v3.w;
        }
        for (; r < cnt; r += 2) {
            float4 v0 = hp[(size_t)r * (H_ / 4)];
            a0.x += v0.x; a0.y += v0.y; a0.z += v0.z; a0.w += v0.w;
        }
        a0.x = (a0.x + a1.x) + (a2.x + a3.x);
        a0.y = (a0.y + a1.y) + (a2.y + a3.y);
        a0.z = (a0.z + a1.z) + (a2.z + a3.z);
        a0.w = (a0.w + a1.w) + (a2.w + a3.w);

        if (grp == 1) red[gcol] = a0;
        __syncthreads();
        if (grp == 0) {
            float4 p = red[gcol];
            float m[4];
            m[0] = (a0.x + p.x) * inv;
            m[1] = (a0.y + p.y) * inv;
            m[2] = (a0.z + p.z) * inv;
            m[3] = (a0.w + p.w) * inv;

            __nv_bfloat16 hi[4], lo[4];
            #pragma unroll
            for (int i = 0; i < 4; ++i) {
                hi[i] = __float2bfloat16(m[i]);
                lo[i] = __float2bfloat16(m[i] - __bfloat162float(hi[i]));
            }
            __nv_bfloat162 ph0 = {hi[0], hi[1]}, ph1 = {hi[2], hi[3]};
            __nv_bfloat162 pl0 = {lo[0], lo[1]}, pl1 = {lo[2], lo[3]};
            uint2 uh, ul;
            uh.x = *(uint32_t*)&ph0; uh.y = *(uint32_t*)&ph1;
            ul.x = *(uint32_t*)&pl0; ul.y = *(uint32_t*)&pl1;
            ((uint2*)g_mean_hi)[(size_t)bid * (H_ / 4) + gcol] = uh;
            ((uint2*)g_mean_lo)[(size_t)bid * (H_ / 4) + gcol] = ul;
        }
    } else {
        __shared__ float t[32][33];
        const int w  = bid - NSEG;
        const int n0 = (w % 24) * 32, k0 = (w / 24) * 32;
        if (tid < 256) {
            const int tx = tid & 31, ty = tid >> 5;
            #pragma unroll
            for (int r = 0; r < 32; r += 8)
                t[ty + r][tx] = W[(size_t)(k0 + ty + r) * H_ + n0 + tx];
        }
        __syncthreads();
        if (tid < 256) {
            const int tx = tid & 31, ty = tid >> 5;
            const int k = k0 + tx;
            #pragma unroll
            for (int r = 0; r < 32; r += 8) {
                const int n = n0 + ty + r;
                float v = t[tx][ty + r];
                __nv_bfloat16 hi = __float2bfloat16(v);
                __nv_bfloat16 lo = __float2bfloat16(v - __bfloat162float(hi));
                g_wt_hi[(size_t)n * H_ + k] = hi;
                g_wt_lo[(size_t)n * H_ + k] = lo;
            }
        }
    }
}

// ---------------------------------------------------------------------------
// Kernel 2: bf16x3 warp-MMA GEMM + bias + SELU + fused partial logits.
// CTA tile 64x96, block = 128 (4 warps: 2M x 2N, warp tile 32x48).
// grid = (8, 16) = 128 CTAs -> exactly 1 CTA/SM, no stragglers.
// K chunks of 64 (12 iterations), 2-stage cp.async pipeline (dynamic smem).
// ---------------------------------------------------------------------------
#define TM 64
#define TN 96
#define KC 64
#define KPAD 72
#define NCHUNK (H_ / KC)   // 12
#define A_STAGE (TM * KPAD)                 // 4608 elems
#define B_STAGE (TN * KPAD)                 // 6912 elems
#define SMEM_BYTES ((2 * 2 * A_STAGE + 2 * 2 * B_STAGE) * 2 + \
                    TN * C_ * 4 + TN * 4)   // 94464

__global__ __launch_bounds__(128) void gemm_fused_kernel(
    const float* __restrict__ bias, const float* __restrict__ Wo) {
    extern __shared__ __align__(16) char dynsmem[];
    __nv_bfloat16* sA_hi = (__nv_bfloat16*)dynsmem;       // [2][TM][KPAD]
    __nv_bfloat16* sA_lo = sA_hi + 2 * A_STAGE;
    __nv_bfloat16* sB_hi = sA_lo + 2 * A_STAGE;           // [2][TN][KPAD]
    __nv_bfloat16* sB_lo = sB_hi + 2 * B_STAGE;
    float* sWo   = (float*)(sB_lo + 2 * B_STAGE);
    float* sBias = sWo + TN * C_;

    const int tid  = threadIdx.x;
    const int wid  = tid >> 5;
    const int lane = tid & 31;
    const int warp_m = wid & 1;     // 32 rows each
    const int warp_n = wid >> 1;    // 48 cols each
    const int n0 = blockIdx.x * TN;
    const int m0 = blockIdx.y * TM;

    for (int i = tid; i < TN * C_; i += 128) sWo[i] = Wo[(size_t)n0 * C_ + i];
    if (tid < TN) sBias[tid] = bias[n0 + tid];

    const __nv_bfloat16* __restrict__ Ahi = g_mean_hi + (size_t)m0 * H_;
    const __nv_bfloat16* __restrict__ Alo = g_mean_lo + (size_t)m0 * H_;
    const __nv_bfloat16* __restrict__ Bhi = g_wt_hi + (size_t)n0 * H_;
    const __nv_bfloat16* __restrict__ Blo = g_wt_lo + (size_t)n0 * H_;

    // copy per stage: A arrays 512 16B-units each, B arrays 768 each.
    auto issue = [&](int st, int k0) {
        #pragma unroll
        for (int i = 0; i < 4; ++i) {
            const int unit = tid + i * 128;          // 0..511
            const int row = unit >> 3, u = unit & 7;
            const size_t goff = (size_t)row * H_ + k0 + u * 8;
            const int soff = (st * TM + row) * KPAD + u * 8;
            CP16(s2u(sA_hi + soff), Ahi + goff);
            CP16(s2u(sA_lo + soff), Alo + goff);
        }
        #pragma unroll
        for (int i = 0; i < 6; ++i) {
            const int unit = tid + i * 128;          // 0..767
            const int row = unit >> 3, u = unit & 7;
            const size_t goff = (size_t)row * H_ + k0 + u * 8;
            const int soff = (st * TN + row) * KPAD + u * 8;
            CP16(s2u(sB_hi + soff), Bhi + goff);
            CP16(s2u(sB_lo + soff), Blo + goff);
        }
    };

    issue(0, 0);
    asm volatile("cp.async.commit_group;" ::: "memory");

    float acc[2][6][4] = {};

    for (int ck = 0; ck < NCHUNK; ++ck) {
        asm volatile("cp.async.wait_group 0;" ::: "memory");
        __syncthreads();
        if (ck + 1 < NCHUNK) issue((ck + 1) & 1, (ck + 1) * KC);
        asm volatile("cp.async.commit_group;" ::: "memory");

        const int st = ck & 1;
        const int abase = st * TM * KPAD;
        const int bbase = st * TN * KPAD;
        #pragma unroll
        for (int ks = 0; ks < KC / 16; ++ks) {
            const int kw = ks * 16;
            uint32_t ah[2][4], al[2][4], bh[3][4], bl[3][4];
            #pragma unroll
            for (int mt = 0; mt < 2; ++mt) {
                int row = warp_m * 32 + mt * 16 + (lane & 15);
                int col = kw + ((lane >> 4) << 3);
                ldsm_x4(ah[mt], s2u(sA_hi + abase + row * KPAD + col));
                ldsm_x4(al[mt], s2u(sA_lo + abase + row * KPAD + col));
            }
            #pragma unroll
            for (int np = 0; np < 3; ++np) {
                int row = warp_n * 48 + np * 16 + (lane & 7) +
                          ((lane >> 4) << 3);
                int col = kw + (((lane >> 3) & 1) << 3);
                ldsm_x4(bh[np], s2u(sB_hi + bbase + row * KPAD + col));
                ldsm_x4(bl[np], s2u(sB_lo + bbase + row * KPAD + col));
            }
            #pragma unroll
            for (int mt = 0; mt < 2; ++mt) {
                #pragma unroll
                for (int nt = 0; nt < 6; ++nt) {
                    const uint32_t* bhp = &bh[nt >> 1][(nt & 1) * 2];
                    const uint32_t* blp = &bl[nt >> 1][(nt & 1) * 2];
                    mma_bf16(acc[mt][nt], ah[mt], bhp);
                    mma_bf16(acc[mt][nt], ah[mt], blp);
                    mma_bf16(acc[mt][nt], al[mt], bhp);
                }
            }
        }
    }

    // ---- epilogue: bias + SELU + partial logits ----
    const float kScale = 1.0507009873554805f;
    const float kAlpha = 1.6732632423543772f;
    float pl[4][C_] = {};   // ridx = mt*2 + upper8
    #pragma unroll
    for (int mt = 0; mt < 2; ++mt) {
        #pragma unroll
        for (int nt = 0; nt < 6; ++nt) {
            #pragma unroll
            for (int e = 0; e < 4; ++e) {
                int col = warp_n * 48 + nt * 8 + (lane & 3) * 2 + (e & 1);
                float x = acc[mt][nt][e] + sBias[col];
                float y = (x > 0.0f) ? x : kAlpha * expm1f(x);
                float h = kScale * y;
                int ridx = mt * 2 + (e >> 1);
                #pragma unroll
                for (int c = 0; c < C_; ++c)
                    pl[ridx][c] = fmaf(h, sWo[col * C_ + c], pl[ridx][c]);
            }
        }
    }
    #pragma unroll
    for (int ridx = 0; ridx < 4; ++ridx)
        #pragma unroll
        for (int c = 0; c < C_; ++c) {
            pl[ridx][c] += __shfl_xor_sync(0xFFFFFFFFu, pl[ridx][c], 1);
            pl[ridx][c] += __shfl_xor_sync(0xFFFFFFFFu, pl[ridx][c], 2);
        }
    if ((lane & 3) == 0) {
        const int slot = blockIdx.x * 2 + warp_n;
        #pragma unroll
        for (int ridx = 0; ridx < 4; ++ridx) {
            int row = m0 + warp_m * 32 + (ridx >> 1) * 16 + (lane >> 2) +
                      (ridx & 1) * 8;
            float* dst = g_partial + ((size_t)slot * NSEG + row) * C_;
            #pragma unroll
            for (int c = 0; c < C_; ++c) dst[c] = pl[ridx][c];
        }
    }
}

// ---------------------------------------------------------------------------
// Kernel 3: reduce 16 partial slots + b_o, softmax.  grid=4, block=256.
// ---------------------------------------------------------------------------
__global__ __launch_bounds__(256) void softmax_kernel(
    const float* __restrict__ bo, float* __restrict__ out) {
    int row = blockIdx.x * 256 + threadIdx.x;
    float l[C_];
    #pragma unroll
    for (int c = 0; c < C_; ++c) l[c] = bo[c];
    #pragma unroll
    for (int t = 0; t < NTILE_P; ++t) {
        const float* p = g_partial + ((size_t)t * NSEG + row) * C_;
        #pragma unroll
        for (int c = 0; c < C_; ++c) l[c] += p[c];
    }
    float mx = -INFINITY;
    #pragma unroll
    for (int c = 0; c < C_; ++c) mx = fmaxf(mx, l[c]);
    float sum = 0.0f;
    #pragma unroll
    for (int c = 0; c < C_; ++c) { l[c] = expf(l[c] - mx); sum += l[c]; }
    float inv = 1.0f / sum;
    #pragma unroll
    for (int c = 0; c < C_; ++c) out[(size_t)row * C_ + c] = l[c] * inv;
}

// ---------------------------------------------------------------------------
// Launch
// ---------------------------------------------------------------------------
extern "C" void kernel_launch(void* const* d_in, const int* in_sizes, int n_in,
                              void* d_out, int out_size) {
    const float* hidden = (const float*)d_in[0];
    const int*   seg    = (const int*)d_in[1];
    int base = (n_in >= 7) ? 3 : 2;
    const float* W_h = (const float*)d_in[base + 0];
    const float* b_h = (const float*)d_in[base + 1];
    const float* W_o = (const float*)d_in[base + 2];
    const float* b_o = (const float*)d_in[base + 3];
    float* out = (float*)d_out;

    cudaFuncSetAttribute(gemm_fused_kernel,
                         cudaFuncAttributeMaxDynamicSharedMemorySize,
                         SMEM_BYTES);

    prep_kernel<<<NSEG + NWPREP, 384>>>(hidden, seg, W_h);

    dim3 gg(NTILE_N, NTILE_M);   // (8, 16) = 128 CTAs
    gemm_fused_kernel<<<gg, 128, SMEM_BYTES>>>(b_h, W_o);

    softmax_kernel<<<NSEG / 256, 256>>>(b_o, out);
}